// round 12
// baseline (speedup 1.0000x reference)
#include <cuda_runtime.h>
#include <math.h>

#define Bx 8
#define Sx 512
#define Hx 768
#define Mx (Bx*Sx)   // 4096
#define H4 (Hx/4)    // 192

// ---------------- device scratch (no allocations allowed) ----------------
__device__ int   g_index;
__device__ float g_w_sel;
__device__ float g_w_rest;
__device__ float g_y[Mx*Hx];        // conv output scratch
__device__ float g_z[Mx*Hx];        // depthwise output scratch
__device__ float g_wt[Hx*Hx*7];     // packed weights [t][i][o]
__device__ float g_psum[64*Hx];
__device__ float g_psq[64*Hx];
__device__ float g_mean[Hx];
__device__ float g_rstd[Hx];

// ---------------- gumbel gate ----------------
__global__ void gate_kernel(const float* __restrict__ u,
                            const float* __restrict__ arch) {
    if (threadIdx.x != 0) return;
    float a[10], l[10], p[10];
    float amax = -1e30f;
    #pragma unroll
    for (int i = 0; i < 10; i++) { a[i] = arch[i]; amax = fmaxf(amax, a[i]); }
    float se = 0.f;
    #pragma unroll
    for (int i = 0; i < 10; i++) se += expf(a[i] - amax);
    float lse = logf(se) + amax;
    #pragma unroll
    for (int i = 0; i < 10; i++) {
        float uc = fminf(fmaxf(u[i], 1e-9f), 1.f - 1e-9f);
        float gum = -logf(-logf(uc));
        l[i] = ((a[i] - lse) + gum) * 0.1f;   // / TEM=10
    }
    float lmax = -1e30f;
    #pragma unroll
    for (int i = 0; i < 10; i++) lmax = fmaxf(lmax, l[i]);
    float ps = 0.f;
    #pragma unroll
    for (int i = 0; i < 10; i++) { p[i] = expf(l[i] - lmax); ps += p[i]; }
    int idx = 0; float best = -1.f;
    #pragma unroll
    for (int i = 0; i < 10; i++) {
        p[i] /= ps;
        if (p[i] > best) { best = p[i]; idx = i; }
    }
    float sum = 0.f, wsel = 0.f;
    #pragma unroll
    for (int i = 0; i < 10; i++) {
        float w = ((i == idx) ? 1.0f : 0.0f) - p[i] + p[i];  // straight-through
        sum += w;
        if (i == idx) wsel = w;
    }
    g_index  = idx;
    g_w_sel  = wsel;
    g_w_rest = sum - wsel;
}

// ---------------- fused prep kernel ----------------
// idx 0,1,2,9 : compute simple branch, write OUT directly (float4).
// idx 3,4,5   : pack selected nor_conv weights w[o][i][t] -> g_wt[t][i][o].
// idx 6,7,8   : depthwise dilated conv -> g_z, and pack pointwise -> g_wt.
__global__ void __launch_bounds__(256) prep_kernel(
        const float* __restrict__ x, float* __restrict__ out,
        const float* __restrict__ w_nor3, const float* __restrict__ w_nor5,
        const float* __restrict__ w_nor7,
        const float* __restrict__ wd3, const float* __restrict__ wp3,
        const float* __restrict__ wd5, const float* __restrict__ wp5,
        const float* __restrict__ wd7, const float* __restrict__ wp7) {
    const int idx = g_index;
    const int tid0 = blockIdx.x * blockDim.x + threadIdx.x;
    const int nthr = gridDim.x * blockDim.x;

    if (idx == 0 || idx == 1 || idx == 2 || idx == 9) {
        const float4* __restrict__ x4 = (const float4*)x;
        float4* __restrict__ o4 = (float4*)out;
        const float ws = g_w_sel, wr = g_w_rest;
        const int N4 = Mx*H4;
        for (int e4 = tid0; e4 < N4; e4 += nthr) {
            int m = e4 / H4;
            int s = m & (Sx - 1);
            float4 xv = x4[e4];
            float4 val;
            if (idx == 0) {
                val = make_float4(0.f, 0.f, 0.f, 0.f);
            } else if (idx == 9) {
                val = xv;
            } else if (idx == 1) {
                float4 xm = (s > 0)      ? x4[e4 - H4] : make_float4(0,0,0,0);
                float4 xp = (s < Sx - 1) ? x4[e4 + H4] : make_float4(0,0,0,0);
                const float r3 = 1.f/3.f;
                val = make_float4((xm.x+xv.x+xp.x)*r3, (xm.y+xv.y+xp.y)*r3,
                                  (xm.z+xv.z+xp.z)*r3, (xm.w+xv.w+xp.w)*r3);
            } else {
                float4 xm = (s > 0)      ? x4[e4 - H4]
                                         : make_float4(-INFINITY,-INFINITY,-INFINITY,-INFINITY);
                float4 xp = (s < Sx - 1) ? x4[e4 + H4]
                                         : make_float4(-INFINITY,-INFINITY,-INFINITY,-INFINITY);
                val = make_float4(fmaxf(xm.x, fmaxf(xv.x, xp.x)),
                                  fmaxf(xm.y, fmaxf(xv.y, xp.y)),
                                  fmaxf(xm.z, fmaxf(xv.z, xp.z)),
                                  fmaxf(xm.w, fmaxf(xv.w, xp.w)));
            }
            o4[e4] = make_float4(ws*val.x + wr + xv.x, ws*val.y + wr + xv.y,
                                 ws*val.z + wr + xv.z, ws*val.w + wr + xv.w);
        }
        return;
    }

    if (idx >= 3 && idx <= 5) {
        const int K = 2*(idx-3) + 3;
        const float* __restrict__ w = (idx == 3) ? w_nor3 : (idx == 4) ? w_nor5 : w_nor7;
        const int NW = Hx*Hx*K;
        for (int e = tid0; e < NW; e += nthr) {
            int o = e % Hx;
            int r = e / Hx;
            int i = r % Hx;
            int t = r / Hx;
            g_wt[e] = w[(o*Hx + i)*K + t];
        }
        return;
    }

    // idx 6..8: depthwise dilated conv + pointwise pack
    {
        const int K = 2*(idx-6) + 3;
        const float* __restrict__ wd = (idx == 6) ? wd3 : (idx == 7) ? wd5 : wd7;
        const float* __restrict__ wp = (idx == 6) ? wp3 : (idx == 7) ? wp5 : wp7;
        // pack pointwise: wp[o][i][0] -> g_wt[i][o]
        for (int e = tid0; e < Hx*Hx; e += nthr) {
            int o = e % Hx;
            int i = e / Hx;
            g_wt[e] = wp[o*Hx + i];
        }
        // depthwise: g_z[m,h] = sum_t wd[h,t]*relu(x[b, s+2t-(K-1), h])
        const int NE = Mx*Hx;
        for (int e = tid0; e < NE; e += nthr) {
            int h = e % Hx;
            int m = e / Hx;
            int s = m & (Sx - 1);
            int b = m >> 9;
            float acc = 0.f;
            for (int t = 0; t < K; t++) {
                int sp = s + 2*t - (K - 1);
                if (sp >= 0 && sp < Sx) {
                    float v = fmaxf(x[(b*Sx + sp)*Hx + h], 0.f);
                    acc += wd[h*K + t] * v;
                }
            }
            g_z[e] = acc;
        }
    }
}

// ---------------- implicit-conv GEMM (runtime params from g_index) ----------------
// BM=64, BN=64, BK=16, 256 threads, 4x4 register tile.
__global__ void __launch_bounds__(256) conv_gemm(const float* __restrict__ x) {
    const int idx = g_index;
    if (idx < 3 || idx > 8) return;

    int K, PAD; bool RELU; const float* __restrict__ A;
    if (idx <= 5) { K = 2*(idx-3)+3; PAD = K/2; RELU = true;  A = x;   }
    else          { K = 1;           PAD = 0;   RELU = false; A = g_z; }

    __shared__ float As[16][64];
    __shared__ float Ws[16][64];
    const int tid = threadIdx.x;
    const int tx = tid & 15, ty = tid >> 4;
    const int row0 = blockIdx.y * 64;
    const int col0 = blockIdx.x * 64;

    const int a_kk  = tid & 15;
    const int a_mm0 = tid >> 4;
    const int w_nn  = tid & 63;
    const int w_kk0 = tid >> 6;

    float acc[4][4] = {};

    for (int t = 0; t < K; t++) {
        const float* __restrict__ wt_t = g_wt + t * Hx * Hx;
        const int soff = t - PAD;
        for (int kb = 0; kb < Hx/16; kb++) {
            #pragma unroll
            for (int i = 0; i < 4; i++) {
                int mm = a_mm0 + 16*i;
                int m  = row0 + mm;
                int s  = m & (Sx - 1);
                int b  = m >> 9;
                int sp = s + soff;
                float v = 0.f;
                if (sp >= 0 && sp < Sx) {
                    v = A[(b*Sx + sp)*Hx + kb*16 + a_kk];
                    if (RELU) v = fmaxf(v, 0.f);
                }
                As[a_kk][mm] = v;
            }
            #pragma unroll
            for (int i = 0; i < 4; i++) {
                int kk = w_kk0 + 4*i;
                Ws[kk][w_nn] = wt_t[(kb*16 + kk)*Hx + col0 + w_nn];
            }
            __syncthreads();
            #pragma unroll
            for (int kk = 0; kk < 16; kk++) {
                float4 av = reinterpret_cast<const float4*>(&As[kk][0])[ty];
                float4 bv = reinterpret_cast<const float4*>(&Ws[kk][0])[tx];
                acc[0][0] += av.x*bv.x; acc[0][1] += av.x*bv.y; acc[0][2] += av.x*bv.z; acc[0][3] += av.x*bv.w;
                acc[1][0] += av.y*bv.x; acc[1][1] += av.y*bv.y; acc[1][2] += av.y*bv.z; acc[1][3] += av.y*bv.w;
                acc[2][0] += av.z*bv.x; acc[2][1] += av.z*bv.y; acc[2][2] += av.z*bv.z; acc[2][3] += av.z*bv.w;
                acc[3][0] += av.w*bv.x; acc[3][1] += av.w*bv.y; acc[3][2] += av.w*bv.z; acc[3][3] += av.w*bv.w;
            }
            __syncthreads();
        }
    }
    #pragma unroll
    for (int i = 0; i < 4; i++) {
        int m = row0 + ty*4 + i;
        #pragma unroll
        for (int j = 0; j < 4; j++)
            g_y[m*Hx + col0 + tx*4 + j] = acc[i][j];
    }
}

// ---------------- BN stats (two-stage deterministic reduction) ----------------
__global__ void bn_stats1() {
    int idx = g_index;
    if (idx < 3 || idx > 8) return;
    int blk = blockIdx.x;            // 64 blocks, 64 rows each
    float s0[3] = {0,0,0}, s1[3] = {0,0,0};
    for (int r = 0; r < 64; r++) {
        int m = blk*64 + r;
        #pragma unroll
        for (int c3 = 0; c3 < 3; c3++) {
            int c = threadIdx.x + 256*c3;
            float v = g_y[m*Hx + c];
            s0[c3] += v;
            s1[c3] += v*v;
        }
    }
    #pragma unroll
    for (int c3 = 0; c3 < 3; c3++) {
        int c = threadIdx.x + 256*c3;
        g_psum[blk*Hx + c] = s0[c3];
        g_psq [blk*Hx + c] = s1[c3];
    }
}

__global__ void bn_stats2() {
    int idx = g_index;
    if (idx < 3 || idx > 8) return;
    int c = blockIdx.x * blockDim.x + threadIdx.x;
    if (c >= Hx) return;
    float s = 0.f, q = 0.f;
    for (int b2 = 0; b2 < 64; b2++) { s += g_psum[b2*Hx + c]; q += g_psq[b2*Hx + c]; }
    float mean = s * (1.f / (float)Mx);
    float var  = q * (1.f / (float)Mx) - mean*mean;
    g_mean[c] = mean;
    g_rstd[c] = rsqrtf(var + 1e-5f);
}

// ---------------- BN apply + residual combine (float4 grid-stride) ----------------
__global__ void __launch_bounds__(256) bn_combine(
        const float* __restrict__ x, float* __restrict__ out,
        const float* g3, const float* bb3,
        const float* g5, const float* bb5,
        const float* g7, const float* bb7,
        const float* gd3, const float* bd3,
        const float* gd5, const float* bd5,
        const float* gd7, const float* bd7) {
    int idx = g_index;
    if (idx < 3 || idx > 8) return;
    const float* gamma; const float* beta;
    switch (idx) {
        case 3: gamma = g3;  beta = bb3; break;
        case 4: gamma = g5;  beta = bb5; break;
        case 5: gamma = g7;  beta = bb7; break;
        case 6: gamma = gd3; beta = bd3; break;
        case 7: gamma = gd5; beta = bd5; break;
        default: gamma = gd7; beta = bd7; break;
    }
    const float4* __restrict__ x4 = (const float4*)x;
    const float4* __restrict__ y4 = (const float4*)g_y;
    const float4* __restrict__ gm4 = (const float4*)g_mean;
    const float4* __restrict__ rs4 = (const float4*)g_rstd;
    const float4* __restrict__ ga4 = (const float4*)gamma;
    const float4* __restrict__ be4 = (const float4*)beta;
    float4* __restrict__ o4 = (float4*)out;
    const float ws = g_w_sel, wr = g_w_rest;
    const int N4 = Mx*H4;
    const int tid0 = blockIdx.x * blockDim.x + threadIdx.x;
    const int nthr = gridDim.x * blockDim.x;
    for (int e4 = tid0; e4 < N4; e4 += nthr) {
        int c4 = e4 % H4;
        float4 y = y4[e4];
        float4 xv = x4[e4];
        float4 mn = gm4[c4], rs = rs4[c4], ga = ga4[c4], be = be4[c4];
        float4 v = make_float4((y.x - mn.x)*rs.x*ga.x + be.x,
                               (y.y - mn.y)*rs.y*ga.y + be.y,
                               (y.z - mn.z)*rs.z*ga.z + be.z,
                               (y.w - mn.w)*rs.w*ga.w + be.w);
        o4[e4] = make_float4(ws*v.x + wr + xv.x, ws*v.y + wr + xv.y,
                             ws*v.z + wr + xv.z, ws*v.w + wr + xv.w);
    }
}

// ---------------- launch ----------------
extern "C" void kernel_launch(void* const* d_in, const int* in_sizes, int n_in,
                              void* d_out, int out_size) {
    const float* x    = (const float*)d_in[0];
    const float* u    = (const float*)d_in[1];
    const float* arch = (const float*)d_in[2];
    const float* w_nor3 = (const float*)d_in[3];
    const float* g_nor3 = (const float*)d_in[4];
    const float* b_nor3 = (const float*)d_in[5];
    const float* w_nor5 = (const float*)d_in[6];
    const float* g_nor5 = (const float*)d_in[7];
    const float* b_nor5 = (const float*)d_in[8];
    const float* w_nor7 = (const float*)d_in[9];
    const float* g_nor7 = (const float*)d_in[10];
    const float* b_nor7 = (const float*)d_in[11];
    const float* wd_dil3 = (const float*)d_in[12];
    const float* wp_dil3 = (const float*)d_in[13];
    const float* g_dil3  = (const float*)d_in[14];
    const float* b_dil3  = (const float*)d_in[15];
    const float* wd_dil5 = (const float*)d_in[16];
    const float* wp_dil5 = (const float*)d_in[17];
    const float* g_dil5  = (const float*)d_in[18];
    const float* b_dil5  = (const float*)d_in[19];
    const float* wd_dil7 = (const float*)d_in[20];
    const float* wp_dil7 = (const float*)d_in[21];
    const float* g_dil7  = (const float*)d_in[22];
    const float* b_dil7  = (const float*)d_in[23];
    float* out = (float*)d_out;

    dim3 gemm_grid(Hx/64, Mx/64);

    gate_kernel<<<1, 32>>>(u, arch);

    prep_kernel<<<1024, 256>>>(x, out,
                               w_nor3, w_nor5, w_nor7,
                               wd_dil3, wp_dil3, wd_dil5, wp_dil5, wd_dil7, wp_dil7);

    conv_gemm<<<gemm_grid, 256>>>(x);

    bn_stats1<<<64, 256>>>();
    bn_stats2<<<3, 256>>>();
    bn_combine<<<1024, 256>>>(x, out,
                              g_nor3, b_nor3, g_nor5, b_nor5, g_nor7, b_nor7,
                              g_dil3, b_dil3, g_dil5, b_dil5, g_dil7, b_dil7);
}

// round 13
// speedup vs baseline: 1.0133x; 1.0133x over previous
#include <cuda_runtime.h>
#include <math.h>

#define Bx 8
#define Sx 512
#define Hx 768
#define Mx (Bx*Sx)   // 4096
#define H4 (Hx/4)    // 192

// ---------------- device scratch (no allocations allowed) ----------------
__device__ int   g_index;
__device__ float g_w_sel;
__device__ float g_w_rest;
__device__ float g_y[Mx*Hx];        // conv output scratch
__device__ float g_z[Mx*Hx];        // depthwise output scratch
__device__ float g_wt[Hx*Hx*7];     // packed weights [t][i][o]
__device__ float g_psum[64*Hx];
__device__ float g_psq[64*Hx];
__device__ float g_mean[Hx];
__device__ float g_rstd[Hx];

// ---------------- gumbel gate ----------------
__global__ void gate_kernel(const float* __restrict__ u,
                            const float* __restrict__ arch) {
    if (threadIdx.x != 0) return;
    float a[10], l[10], p[10];
    float amax = -1e30f;
    #pragma unroll
    for (int i = 0; i < 10; i++) { a[i] = arch[i]; amax = fmaxf(amax, a[i]); }
    float se = 0.f;
    #pragma unroll
    for (int i = 0; i < 10; i++) se += expf(a[i] - amax);
    float lse = logf(se) + amax;
    #pragma unroll
    for (int i = 0; i < 10; i++) {
        float uc = fminf(fmaxf(u[i], 1e-9f), 1.f - 1e-9f);
        float gum = -logf(-logf(uc));
        l[i] = ((a[i] - lse) + gum) * 0.1f;   // / TEM=10
    }
    float lmax = -1e30f;
    #pragma unroll
    for (int i = 0; i < 10; i++) lmax = fmaxf(lmax, l[i]);
    float ps = 0.f;
    #pragma unroll
    for (int i = 0; i < 10; i++) { p[i] = expf(l[i] - lmax); ps += p[i]; }
    int idx = 0; float best = -1.f;
    #pragma unroll
    for (int i = 0; i < 10; i++) {
        p[i] /= ps;
        if (p[i] > best) { best = p[i]; idx = i; }
    }
    float sum = 0.f, wsel = 0.f;
    #pragma unroll
    for (int i = 0; i < 10; i++) {
        float w = ((i == idx) ? 1.0f : 0.0f) - p[i] + p[i];  // straight-through
        sum += w;
        if (i == idx) wsel = w;
    }
    g_index  = idx;
    g_w_sel  = wsel;
    g_w_rest = sum - wsel;
}

// ---------------- fused prep kernel ----------------
// idx 0,1,2,9 : compute simple branch, write OUT directly (float4).
// idx 3,4,5   : pack selected nor_conv weights w[o][i][t] -> g_wt[t][i][o].
// idx 6,7,8   : depthwise dilated conv -> g_z, and pack pointwise -> g_wt.
__global__ void __launch_bounds__(256) prep_kernel(
        const float* __restrict__ x, float* __restrict__ out,
        const float* __restrict__ w_nor3, const float* __restrict__ w_nor5,
        const float* __restrict__ w_nor7,
        const float* __restrict__ wd3, const float* __restrict__ wp3,
        const float* __restrict__ wd5, const float* __restrict__ wp5,
        const float* __restrict__ wd7, const float* __restrict__ wp7) {
    const int idx = g_index;
    const int tid0 = blockIdx.x * blockDim.x + threadIdx.x;
    const int nthr = gridDim.x * blockDim.x;

    if (idx == 0 || idx == 1 || idx == 2 || idx == 9) {
        const float4* __restrict__ x4 = (const float4*)x;
        float4* __restrict__ o4 = (float4*)out;
        const float ws = g_w_sel, wr = g_w_rest;
        const int N4 = Mx*H4;
        for (int e4 = tid0; e4 < N4; e4 += nthr) {
            int m = e4 / H4;
            int s = m & (Sx - 1);
            float4 xv = x4[e4];
            float4 val;
            if (idx == 0) {
                val = make_float4(0.f, 0.f, 0.f, 0.f);
            } else if (idx == 9) {
                val = xv;
            } else if (idx == 1) {
                float4 xm = (s > 0)      ? x4[e4 - H4] : make_float4(0,0,0,0);
                float4 xp = (s < Sx - 1) ? x4[e4 + H4] : make_float4(0,0,0,0);
                const float r3 = 1.f/3.f;
                val = make_float4((xm.x+xv.x+xp.x)*r3, (xm.y+xv.y+xp.y)*r3,
                                  (xm.z+xv.z+xp.z)*r3, (xm.w+xv.w+xp.w)*r3);
            } else {
                float4 xm = (s > 0)      ? x4[e4 - H4]
                                         : make_float4(-INFINITY,-INFINITY,-INFINITY,-INFINITY);
                float4 xp = (s < Sx - 1) ? x4[e4 + H4]
                                         : make_float4(-INFINITY,-INFINITY,-INFINITY,-INFINITY);
                val = make_float4(fmaxf(xm.x, fmaxf(xv.x, xp.x)),
                                  fmaxf(xm.y, fmaxf(xv.y, xp.y)),
                                  fmaxf(xm.z, fmaxf(xv.z, xp.z)),
                                  fmaxf(xm.w, fmaxf(xv.w, xp.w)));
            }
            o4[e4] = make_float4(ws*val.x + wr + xv.x, ws*val.y + wr + xv.y,
                                 ws*val.z + wr + xv.z, ws*val.w + wr + xv.w);
        }
        return;
    }

    if (idx >= 3 && idx <= 5) {
        const int K = 2*(idx-3) + 3;
        const float* __restrict__ w = (idx == 3) ? w_nor3 : (idx == 4) ? w_nor5 : w_nor7;
        const int NW = Hx*Hx*K;
        for (int e = tid0; e < NW; e += nthr) {
            int o = e % Hx;
            int r = e / Hx;
            int i = r % Hx;
            int t = r / Hx;
            g_wt[e] = w[(o*Hx + i)*K + t];
        }
        return;
    }

    // idx 6..8: depthwise dilated conv + pointwise pack
    {
        const int K = 2*(idx-6) + 3;
        const float* __restrict__ wd = (idx == 6) ? wd3 : (idx == 7) ? wd5 : wd7;
        const float* __restrict__ wp = (idx == 6) ? wp3 : (idx == 7) ? wp5 : wp7;
        // pack pointwise: wp[o][i][0] -> g_wt[i][o]
        for (int e = tid0; e < Hx*Hx; e += nthr) {
            int o = e % Hx;
            int i = e / Hx;
            g_wt[e] = wp[o*Hx + i];
        }
        // depthwise: g_z[m,h] = sum_t wd[h,t]*relu(x[b, s+2t-(K-1), h])
        const int NE = Mx*Hx;
        for (int e = tid0; e < NE; e += nthr) {
            int h = e % Hx;
            int m = e / Hx;
            int s = m & (Sx - 1);
            int b = m >> 9;
            float acc = 0.f;
            for (int t = 0; t < K; t++) {
                int sp = s + 2*t - (K - 1);
                if (sp >= 0 && sp < Sx) {
                    float v = fmaxf(x[(b*Sx + sp)*Hx + h], 0.f);
                    acc += wd[h*K + t] * v;
                }
            }
            g_z[e] = acc;
        }
    }
}

// ---------------- implicit-conv GEMM (runtime params from g_index) ----------------
// BM=64, BN=64, BK=16, 256 threads, 4x4 register tile.
__global__ void __launch_bounds__(256) conv_gemm(const float* __restrict__ x) {
    const int idx = g_index;
    if (idx < 3 || idx > 8) return;

    int K, PAD; bool RELU; const float* __restrict__ A;
    if (idx <= 5) { K = 2*(idx-3)+3; PAD = K/2; RELU = true;  A = x;   }
    else          { K = 1;           PAD = 0;   RELU = false; A = g_z; }

    __shared__ float As[16][64];
    __shared__ float Ws[16][64];
    const int tid = threadIdx.x;
    const int tx = tid & 15, ty = tid >> 4;
    const int row0 = blockIdx.y * 64;
    const int col0 = blockIdx.x * 64;

    const int a_kk  = tid & 15;
    const int a_mm0 = tid >> 4;
    const int w_nn  = tid & 63;
    const int w_kk0 = tid >> 6;

    float acc[4][4] = {};

    for (int t = 0; t < K; t++) {
        const float* __restrict__ wt_t = g_wt + t * Hx * Hx;
        const int soff = t - PAD;
        for (int kb = 0; kb < Hx/16; kb++) {
            #pragma unroll
            for (int i = 0; i < 4; i++) {
                int mm = a_mm0 + 16*i;
                int m  = row0 + mm;
                int s  = m & (Sx - 1);
                int b  = m >> 9;
                int sp = s + soff;
                float v = 0.f;
                if (sp >= 0 && sp < Sx) {
                    v = A[(b*Sx + sp)*Hx + kb*16 + a_kk];
                    if (RELU) v = fmaxf(v, 0.f);
                }
                As[a_kk][mm] = v;
            }
            #pragma unroll
            for (int i = 0; i < 4; i++) {
                int kk = w_kk0 + 4*i;
                Ws[kk][w_nn] = wt_t[(kb*16 + kk)*Hx + col0 + w_nn];
            }
            __syncthreads();
            #pragma unroll
            for (int kk = 0; kk < 16; kk++) {
                float4 av = reinterpret_cast<const float4*>(&As[kk][0])[ty];
                float4 bv = reinterpret_cast<const float4*>(&Ws[kk][0])[tx];
                acc[0][0] += av.x*bv.x; acc[0][1] += av.x*bv.y; acc[0][2] += av.x*bv.z; acc[0][3] += av.x*bv.w;
                acc[1][0] += av.y*bv.x; acc[1][1] += av.y*bv.y; acc[1][2] += av.y*bv.z; acc[1][3] += av.y*bv.w;
                acc[2][0] += av.z*bv.x; acc[2][1] += av.z*bv.y; acc[2][2] += av.z*bv.z; acc[2][3] += av.z*bv.w;
                acc[3][0] += av.w*bv.x; acc[3][1] += av.w*bv.y; acc[3][2] += av.w*bv.z; acc[3][3] += av.w*bv.w;
            }
            __syncthreads();
        }
    }
    #pragma unroll
    for (int i = 0; i < 4; i++) {
        int m = row0 + ty*4 + i;
        #pragma unroll
        for (int j = 0; j < 4; j++)
            g_y[m*Hx + col0 + tx*4 + j] = acc[i][j];
    }
}

// ---------------- BN stats (two-stage deterministic reduction) ----------------
__global__ void bn_stats1() {
    int idx = g_index;
    if (idx < 3 || idx > 8) return;
    int blk = blockIdx.x;            // 64 blocks, 64 rows each
    float s0[3] = {0,0,0}, s1[3] = {0,0,0};
    for (int r = 0; r < 64; r++) {
        int m = blk*64 + r;
        #pragma unroll
        for (int c3 = 0; c3 < 3; c3++) {
            int c = threadIdx.x + 256*c3;
            float v = g_y[m*Hx + c];
            s0[c3] += v;
            s1[c3] += v*v;
        }
    }
    #pragma unroll
    for (int c3 = 0; c3 < 3; c3++) {
        int c = threadIdx.x + 256*c3;
        g_psum[blk*Hx + c] = s0[c3];
        g_psq [blk*Hx + c] = s1[c3];
    }
}

__global__ void bn_stats2() {
    int idx = g_index;
    if (idx < 3 || idx > 8) return;
    int c = blockIdx.x * blockDim.x + threadIdx.x;
    if (c >= Hx) return;
    float s = 0.f, q = 0.f;
    for (int b2 = 0; b2 < 64; b2++) { s += g_psum[b2*Hx + c]; q += g_psq[b2*Hx + c]; }
    float mean = s * (1.f / (float)Mx);
    float var  = q * (1.f / (float)Mx) - mean*mean;
    g_mean[c] = mean;
    g_rstd[c] = rsqrtf(var + 1e-5f);
}

// ---------------- BN apply + residual combine (float4 grid-stride) ----------------
__global__ void __launch_bounds__(256) bn_combine(
        const float* __restrict__ x, float* __restrict__ out,
        const float* g3, const float* bb3,
        const float* g5, const float* bb5,
        const float* g7, const float* bb7,
        const float* gd3, const float* bd3,
        const float* gd5, const float* bd5,
        const float* gd7, const float* bd7) {
    int idx = g_index;
    if (idx < 3 || idx > 8) return;
    const float* gamma; const float* beta;
    switch (idx) {
        case 3: gamma = g3;  beta = bb3; break;
        case 4: gamma = g5;  beta = bb5; break;
        case 5: gamma = g7;  beta = bb7; break;
        case 6: gamma = gd3; beta = bd3; break;
        case 7: gamma = gd5; beta = bd5; break;
        default: gamma = gd7; beta = bd7; break;
    }
    const float4* __restrict__ x4 = (const float4*)x;
    const float4* __restrict__ y4 = (const float4*)g_y;
    const float4* __restrict__ gm4 = (const float4*)g_mean;
    const float4* __restrict__ rs4 = (const float4*)g_rstd;
    const float4* __restrict__ ga4 = (const float4*)gamma;
    const float4* __restrict__ be4 = (const float4*)beta;
    float4* __restrict__ o4 = (float4*)out;
    const float ws = g_w_sel, wr = g_w_rest;
    const int N4 = Mx*H4;
    const int tid0 = blockIdx.x * blockDim.x + threadIdx.x;
    const int nthr = gridDim.x * blockDim.x;
    for (int e4 = tid0; e4 < N4; e4 += nthr) {
        int c4 = e4 % H4;
        float4 y = y4[e4];
        float4 xv = x4[e4];
        float4 mn = gm4[c4], rs = rs4[c4], ga = ga4[c4], be = be4[c4];
        float4 v = make_float4((y.x - mn.x)*rs.x*ga.x + be.x,
                               (y.y - mn.y)*rs.y*ga.y + be.y,
                               (y.z - mn.z)*rs.z*ga.z + be.z,
                               (y.w - mn.w)*rs.w*ga.w + be.w);
        o4[e4] = make_float4(ws*v.x + wr + xv.x, ws*v.y + wr + xv.y,
                             ws*v.z + wr + xv.z, ws*v.w + wr + xv.w);
    }
}

// ---------------- launch ----------------
extern "C" void kernel_launch(void* const* d_in, const int* in_sizes, int n_in,
                              void* d_out, int out_size) {
    const float* x    = (const float*)d_in[0];
    const float* u    = (const float*)d_in[1];
    const float* arch = (const float*)d_in[2];
    const float* w_nor3 = (const float*)d_in[3];
    const float* g_nor3 = (const float*)d_in[4];
    const float* b_nor3 = (const float*)d_in[5];
    const float* w_nor5 = (const float*)d_in[6];
    const float* g_nor5 = (const float*)d_in[7];
    const float* b_nor5 = (const float*)d_in[8];
    const float* w_nor7 = (const float*)d_in[9];
    const float* g_nor7 = (const float*)d_in[10];
    const float* b_nor7 = (const float*)d_in[11];
    const float* wd_dil3 = (const float*)d_in[12];
    const float* wp_dil3 = (const float*)d_in[13];
    const float* g_dil3  = (const float*)d_in[14];
    const float* b_dil3  = (const float*)d_in[15];
    const float* wd_dil5 = (const float*)d_in[16];
    const float* wp_dil5 = (const float*)d_in[17];
    const float* g_dil5  = (const float*)d_in[18];
    const float* b_dil5  = (const float*)d_in[19];
    const float* wd_dil7 = (const float*)d_in[20];
    const float* wp_dil7 = (const float*)d_in[21];
    const float* g_dil7  = (const float*)d_in[22];
    const float* b_dil7  = (const float*)d_in[23];
    float* out = (float*)d_out;

    dim3 gemm_grid(Hx/64, Mx/64);

    gate_kernel<<<1, 32>>>(u, arch);

    prep_kernel<<<1024, 256>>>(x, out,
                               w_nor3, w_nor5, w_nor7,
                               wd_dil3, wp_dil3, wd_dil5, wp_dil5, wd_dil7, wp_dil7);

    conv_gemm<<<gemm_grid, 256>>>(x);

    bn_stats1<<<64, 256>>>();
    bn_stats2<<<3, 256>>>();
    bn_combine<<<1024, 256>>>(x, out,
                              g_nor3, b_nor3, g_nor5, b_nor5, g_nor7, b_nor7,
                              g_dil3, b_dil3, g_dil5, b_dil5, g_dil7, b_dil7);
}

// round 15
// speedup vs baseline: 1.9669x; 1.9412x over previous
#include <cuda_runtime.h>
#include <math.h>

#define Bx 8
#define Sx 512
#define Hx 768
#define Mx (Bx*Sx)   // 4096
#define H4 (Hx/4)    // 192
#define NBLK 296     // 2 per SM on 148 SMs -> guaranteed co-resident
#define NTHR 256

// ---------------- device scratch (no allocations allowed) ----------------
__device__ float g_y[Mx*Hx];        // conv output scratch
__device__ float g_z[Mx*Hx];        // depthwise output scratch
__device__ float g_wt[Hx*Hx*7];     // packed weights [t][i][o]
__device__ float g_psum[64*Hx];
__device__ float g_psq[64*Hx];
__device__ float g_mean[Hx];
__device__ float g_rstd[Hx];

// software grid barrier state (monotonic sense survives graph replays)
__device__ unsigned g_cnt = 0;
__device__ volatile unsigned g_sense = 0;

__device__ __forceinline__ void grid_sync() {
    __threadfence();            // release: all this thread's prior writes -> L2
    __syncthreads();            // all block threads' fences done
    if (threadIdx.x == 0) {
        unsigned s = g_sense;
        unsigned old = atomicAdd(&g_cnt, 1);
        if (old == (unsigned)(gridDim.x - 1)) {
            g_cnt = 0;
            __threadfence();
            g_sense = s + 1;
        } else {
            while (g_sense == s) { }
        }
        __threadfence();        // acquire
    }
    __syncthreads();
}

__global__ void __launch_bounds__(NTHR, 2) fused_kernel(
        const float* __restrict__ x, float* __restrict__ out,
        const float* __restrict__ u, const float* __restrict__ arch,
        const float* __restrict__ w_nor3, const float* __restrict__ g_nor3, const float* __restrict__ b_nor3,
        const float* __restrict__ w_nor5, const float* __restrict__ g_nor5, const float* __restrict__ b_nor5,
        const float* __restrict__ w_nor7, const float* __restrict__ g_nor7, const float* __restrict__ b_nor7,
        const float* __restrict__ wd3, const float* __restrict__ wp3,
        const float* __restrict__ gd3, const float* __restrict__ bd3,
        const float* __restrict__ wd5, const float* __restrict__ wp5,
        const float* __restrict__ gd5, const float* __restrict__ bd5,
        const float* __restrict__ wd7, const float* __restrict__ wp7,
        const float* __restrict__ gd7, const float* __restrict__ bd7) {

    // ---- gate: every block computes it redundantly (10 elements) ----
    __shared__ int   s_idx;
    __shared__ float s_wsel, s_wrest;
    if (threadIdx.x == 0) {
        float a[10], l[10], p[10];
        float amax = -1e30f;
        #pragma unroll
        for (int i = 0; i < 10; i++) { a[i] = arch[i]; amax = fmaxf(amax, a[i]); }
        float se = 0.f;
        #pragma unroll
        for (int i = 0; i < 10; i++) se += expf(a[i] - amax);
        float lse = logf(se) + amax;
        #pragma unroll
        for (int i = 0; i < 10; i++) {
            float uc = fminf(fmaxf(u[i], 1e-9f), 1.f - 1e-9f);
            float gum = -logf(-logf(uc));
            l[i] = ((a[i] - lse) + gum) * 0.1f;     // / TEM=10
        }
        float lmax = -1e30f;
        #pragma unroll
        for (int i = 0; i < 10; i++) lmax = fmaxf(lmax, l[i]);
        float ps = 0.f;
        #pragma unroll
        for (int i = 0; i < 10; i++) { p[i] = expf(l[i] - lmax); ps += p[i]; }
        int idx = 0; float best = -1.f;
        #pragma unroll
        for (int i = 0; i < 10; i++) {
            p[i] /= ps;
            if (p[i] > best) { best = p[i]; idx = i; }
        }
        float sum = 0.f, wsel = 0.f;
        #pragma unroll
        for (int i = 0; i < 10; i++) {
            float w = ((i == idx) ? 1.0f : 0.0f) - p[i] + p[i];  // straight-through
            sum += w;
            if (i == idx) wsel = w;
        }
        s_idx = idx; s_wsel = wsel; s_wrest = sum - wsel;
    }
    __syncthreads();
    const int idx = s_idx;
    const float ws = s_wsel, wr = s_wrest;

    const int tid0 = blockIdx.x * blockDim.x + threadIdx.x;
    const int nthr = gridDim.x * blockDim.x;

    // ================= simple branches: none/avg/max/skip =================
    if (idx == 0 || idx == 1 || idx == 2 || idx == 9) {
        const float4* __restrict__ x4 = (const float4*)x;
        float4* __restrict__ o4 = (float4*)out;
        const int N4 = Mx*H4;
        for (int e4 = tid0; e4 < N4; e4 += nthr) {
            int m = e4 / H4;
            int s = m & (Sx - 1);
            float4 xv = x4[e4];
            float4 val;
            if (idx == 0) {
                val = make_float4(0.f, 0.f, 0.f, 0.f);
            } else if (idx == 9) {
                val = xv;
            } else if (idx == 1) {
                float4 xm = (s > 0)      ? x4[e4 - H4] : make_float4(0,0,0,0);
                float4 xp = (s < Sx - 1) ? x4[e4 + H4] : make_float4(0,0,0,0);
                const float r3 = 1.f/3.f;
                val = make_float4((xm.x+xv.x+xp.x)*r3, (xm.y+xv.y+xp.y)*r3,
                                  (xm.z+xv.z+xp.z)*r3, (xm.w+xv.w+xp.w)*r3);
            } else {
                float4 xm = (s > 0)      ? x4[e4 - H4]
                                         : make_float4(-INFINITY,-INFINITY,-INFINITY,-INFINITY);
                float4 xp = (s < Sx - 1) ? x4[e4 + H4]
                                         : make_float4(-INFINITY,-INFINITY,-INFINITY,-INFINITY);
                val = make_float4(fmaxf(xm.x, fmaxf(xv.x, xp.x)),
                                  fmaxf(xm.y, fmaxf(xv.y, xp.y)),
                                  fmaxf(xm.z, fmaxf(xv.z, xp.z)),
                                  fmaxf(xm.w, fmaxf(xv.w, xp.w)));
            }
            o4[e4] = make_float4(ws*val.x + wr + xv.x, ws*val.y + wr + xv.y,
                                 ws*val.z + wr + xv.z, ws*val.w + wr + xv.w);
        }
        return;   // no barriers on this path
    }

    // ================= conv branches (3..8): persistent pipeline =================
    int K, PAD; bool RELU; const float* __restrict__ A;
    const float* gamma; const float* beta;
    if (idx <= 5) {
        K = 2*(idx-3)+3; PAD = K/2; RELU = true; A = x;
        gamma = (idx == 3) ? g_nor3 : (idx == 4) ? g_nor5 : g_nor7;
        beta  = (idx == 3) ? b_nor3 : (idx == 4) ? b_nor5 : b_nor7;
    } else {
        K = 1; PAD = 0; RELU = false; A = g_z;
        gamma = (idx == 6) ? gd3 : (idx == 7) ? gd5 : gd7;
        beta  = (idx == 6) ? bd3 : (idx == 7) ? bd5 : bd7;
    }

    // ---- phase 1: pack weights (+ depthwise for dil branches) ----
    if (idx <= 5) {
        const int KW = 2*(idx-3) + 3;
        const float* __restrict__ w = (idx == 3) ? w_nor3 : (idx == 4) ? w_nor5 : w_nor7;
        const int NW = Hx*Hx*KW;
        for (int e = tid0; e < NW; e += nthr) {
            int o = e % Hx;
            int r = e / Hx;
            int i = r % Hx;
            int t = r / Hx;
            g_wt[e] = w[(o*Hx + i)*KW + t];
        }
    } else {
        const int KD = 2*(idx-6) + 3;
        const float* __restrict__ wd = (idx == 6) ? wd3 : (idx == 7) ? wd5 : wd7;
        const float* __restrict__ wp = (idx == 6) ? wp3 : (idx == 7) ? wp5 : wp7;
        for (int e = tid0; e < Hx*Hx; e += nthr) {
            int o = e % Hx;
            int i = e / Hx;
            g_wt[e] = wp[o*Hx + i];
        }
        const int NE = Mx*Hx;
        for (int e = tid0; e < NE; e += nthr) {
            int h = e % Hx;
            int m = e / Hx;
            int s = m & (Sx - 1);
            int b = m >> 9;
            float acc = 0.f;
            for (int t = 0; t < KD; t++) {
                int sp = s + 2*t - (KD - 1);
                if (sp >= 0 && sp < Sx) {
                    float v = fmaxf(x[(b*Sx + sp)*Hx + h], 0.f);
                    acc += wd[h*KD + t] * v;
                }
            }
            g_z[e] = acc;
        }
    }
    grid_sync();

    // ---- phase 2: implicit-conv GEMM, tile loop over 64x12 tiles ----
    {
        __shared__ float As[16][64];
        __shared__ float Ws[16][64];
        const int tid = threadIdx.x;
        const int tx = tid & 15, ty = tid >> 4;
        const int a_kk  = tid & 15;
        const int a_mm0 = tid >> 4;
        const int w_nn  = tid & 63;
        const int w_kk0 = tid >> 6;
        const int NTILE = (Mx/64) * (Hx/64);   // 768

        for (int tile = blockIdx.x; tile < NTILE; tile += gridDim.x) {
            const int row0 = (tile / (Hx/64)) * 64;
            const int col0 = (tile % (Hx/64)) * 64;
            float acc[4][4] = {};

            for (int t = 0; t < K; t++) {
                const float* __restrict__ wt_t = g_wt + t * Hx * Hx;
                const int soff = t - PAD;
                for (int kb = 0; kb < Hx/16; kb++) {
                    #pragma unroll
                    for (int i = 0; i < 4; i++) {
                        int mm = a_mm0 + 16*i;
                        int m  = row0 + mm;
                        int s  = m & (Sx - 1);
                        int b  = m >> 9;
                        int sp = s + soff;
                        float v = 0.f;
                        if (sp >= 0 && sp < Sx) {
                            v = A[(b*Sx + sp)*Hx + kb*16 + a_kk];
                            if (RELU) v = fmaxf(v, 0.f);
                        }
                        As[a_kk][mm] = v;
                    }
                    #pragma unroll
                    for (int i = 0; i < 4; i++) {
                        int kk = w_kk0 + 4*i;
                        Ws[kk][w_nn] = wt_t[(kb*16 + kk)*Hx + col0 + w_nn];
                    }
                    __syncthreads();
                    #pragma unroll
                    for (int kk = 0; kk < 16; kk++) {
                        float4 av = reinterpret_cast<const float4*>(&As[kk][0])[ty];
                        float4 bv = reinterpret_cast<const float4*>(&Ws[kk][0])[tx];
                        acc[0][0] += av.x*bv.x; acc[0][1] += av.x*bv.y; acc[0][2] += av.x*bv.z; acc[0][3] += av.x*bv.w;
                        acc[1][0] += av.y*bv.x; acc[1][1] += av.y*bv.y; acc[1][2] += av.y*bv.z; acc[1][3] += av.y*bv.w;
                        acc[2][0] += av.z*bv.x; acc[2][1] += av.z*bv.y; acc[2][2] += av.z*bv.z; acc[2][3] += av.z*bv.w;
                        acc[3][0] += av.w*bv.x; acc[3][1] += av.w*bv.y; acc[3][2] += av.w*bv.z; acc[3][3] += av.w*bv.w;
                    }
                    __syncthreads();
                }
            }
            #pragma unroll
            for (int i = 0; i < 4; i++) {
                int m = row0 + ty*4 + i;
                #pragma unroll
                for (int j = 0; j < 4; j++)
                    g_y[m*Hx + col0 + tx*4 + j] = acc[i][j];
            }
        }
    }
    grid_sync();

    // ---- phase 3: BN stats stage 1 (64 row-chunks of 64 rows) ----
    for (int blk = blockIdx.x; blk < 64; blk += gridDim.x) {
        float s0[3] = {0,0,0}, s1[3] = {0,0,0};
        for (int r = 0; r < 64; r++) {
            int m = blk*64 + r;
            #pragma unroll
            for (int c3 = 0; c3 < 3; c3++) {
                int c = threadIdx.x + 256*c3;
                float v = g_y[m*Hx + c];
                s0[c3] += v;
                s1[c3] += v*v;
            }
        }
        #pragma unroll
        for (int c3 = 0; c3 < 3; c3++) {
            int c = threadIdx.x + 256*c3;
            g_psum[blk*Hx + c] = s0[c3];
            g_psq [blk*Hx + c] = s1[c3];
        }
    }
    grid_sync();

    // ---- phase 4: BN stats stage 2 (768 channels) ----
    for (int c = tid0; c < Hx; c += nthr) {
        float s = 0.f, q = 0.f;
        for (int b2 = 0; b2 < 64; b2++) { s += g_psum[b2*Hx + c]; q += g_psq[b2*Hx + c]; }
        float mean = s * (1.f / (float)Mx);
        float var  = q * (1.f / (float)Mx) - mean*mean;
        g_mean[c] = mean;
        g_rstd[c] = rsqrtf(var + 1e-5f);
    }
    grid_sync();

    // ---- phase 5: BN apply + residual combine ----
    {
        const float4* __restrict__ x4 = (const float4*)x;
        const float4* __restrict__ y4 = (const float4*)g_y;
        const float4* __restrict__ gm4 = (const float4*)g_mean;
        const float4* __restrict__ rs4 = (const float4*)g_rstd;
        const float4* __restrict__ ga4 = (const float4*)gamma;
        const float4* __restrict__ be4 = (const float4*)beta;
        float4* __restrict__ o4 = (float4*)out;
        const int N4 = Mx*H4;
        for (int e4 = tid0; e4 < N4; e4 += nthr) {
            int c4 = e4 % H4;
            float4 y = y4[e4];
            float4 xv = x4[e4];
            float4 mn = gm4[c4], rs = rs4[c4], ga = ga4[c4], be = be4[c4];
            float4 v = make_float4((y.x - mn.x)*rs.x*ga.x + be.x,
                                   (y.y - mn.y)*rs.y*ga.y + be.y,
                                   (y.z - mn.z)*rs.z*ga.z + be.z,
                                   (y.w - mn.w)*rs.w*ga.w + be.w);
            o4[e4] = make_float4(ws*v.x + wr + xv.x, ws*v.y + wr + xv.y,
                                 ws*v.z + wr + xv.z, ws*v.w + wr + xv.w);
        }
    }
}

// ---------------- launch ----------------
extern "C" void kernel_launch(void* const* d_in, const int* in_sizes, int n_in,
                              void* d_out, int out_size) {
    const float* x    = (const float*)d_in[0];
    const float* u    = (const float*)d_in[1];
    const float* arch = (const float*)d_in[2];

    fused_kernel<<<NBLK, NTHR>>>(
        x, (float*)d_out, u, arch,
        (const float*)d_in[3],  (const float*)d_in[4],  (const float*)d_in[5],
        (const float*)d_in[6],  (const float*)d_in[7],  (const float*)d_in[8],
        (const float*)d_in[9],  (const float*)d_in[10], (const float*)d_in[11],
        (const float*)d_in[12], (const float*)d_in[13], (const float*)d_in[14], (const float*)d_in[15],
        (const float*)d_in[16], (const float*)d_in[17], (const float*)d_in[18], (const float*)d_in[19],
        (const float*)d_in[20], (const float*)d_in[21], (const float*)d_in[22], (const float*)d_in[23]);
}